// round 6
// baseline (speedup 1.0000x reference)
#include <cuda_runtime.h>

// TSM temporal shift: x shape (bt=128, c=96, h=56, w=56), N_FRAME=8, fold=32.
// out[b,t,c] = x[b,t+1,c] for c in [0,32)   (zero at t=7)
// out[b,t,c] = x[b,t-1,c] for c in [32,64)  (zero at t=0)
// out[b,t,c] = x[b,t,c]   for c in [64,96)
//
// Pure bandwidth. R3: persistent flat grid (1184 CTAs = 148 SMs x 8) looping
// over all 12288 planes -> no wave relaunch, no fractional tail wave. Body
// keeps R2's front-batched LDG.128.CS (MLP=4) then STG.CS.

#define C_DIM     96
#define N_FRAME   8
#define FOLD      32
#define HW4       784          // 56*56/4
#define N_PLANES  12288        // 128*96
#define GRID      1184         // 148 SMs * 8 CTAs

__global__ __launch_bounds__(256) void tsm_shift_kernel(
    const float4* __restrict__ x, float4* __restrict__ out)
{
    const int tid = threadIdx.x;
    const bool tail = (tid < HW4 - 3 * 256);   // tid < 16

    for (int plane = blockIdx.x; plane < N_PLANES; plane += GRID) {
        const int c = plane % C_DIM;
        const int t = (plane / C_DIM) % N_FRAME;

        const float4* src = x + (size_t)plane * HW4;
        bool zero = false;
        if (c < FOLD) {
            if (t < N_FRAME - 1) src += (size_t)C_DIM * HW4;   // read t+1
            else zero = true;
        } else if (c < 2 * FOLD) {
            if (t > 0) src -= (size_t)C_DIM * HW4;             // read t-1
            else zero = true;
        }

        float4* dst = out + (size_t)plane * HW4;

        if (!zero) {
            float4 v0 = __ldcs(src + tid);
            float4 v1 = __ldcs(src + tid + 256);
            float4 v2 = __ldcs(src + tid + 512);
            float4 v3;
            if (tail) v3 = __ldcs(src + tid + 768);
            __stcs(dst + tid,       v0);
            __stcs(dst + tid + 256, v1);
            __stcs(dst + tid + 512, v2);
            if (tail) __stcs(dst + tid + 768, v3);
        } else {
            const float4 z = make_float4(0.f, 0.f, 0.f, 0.f);
            __stcs(dst + tid,       z);
            __stcs(dst + tid + 256, z);
            __stcs(dst + tid + 512, z);
            if (tail) __stcs(dst + tid + 768, z);
        }
    }
}

extern "C" void kernel_launch(void* const* d_in, const int* in_sizes, int n_in,
                              void* d_out, int out_size)
{
    const float4* x = (const float4*)d_in[0];
    float4* out = (float4*)d_out;
    tsm_shift_kernel<<<GRID, 256>>>(x, out);
}

// round 8
// speedup vs baseline: 1.1290x; 1.1290x over previous
#include <cuda_runtime.h>

// TSM temporal shift: x shape (bt=128, c=96, h=56, w=56), N_FRAME=8, fold=32.
// out[b,t,c] = x[b,t+1,c] for c in [0,32)   (zero at t=7)
// out[b,t,c] = x[b,t-1,c] for c in [32,64)  (zero at t=0)
// out[b,t,c] = x[b,t,c]   for c in [64,96)
//
// Pure bandwidth. R7: one-shot grid (persistent loop regressed in R6), but
// 2 consecutive planes per CTA with all 8 LDG.128.CS front-batched before
// any STG -> per-thread MLP 8. launch_bounds caps regs so occ stays >= 6/SM.

#define C_DIM     96
#define N_FRAME   8
#define FOLD      32
#define HW4       784          // 56*56/4
#define N_PLANES  12288        // 128*96

__device__ __forceinline__ const float4* src_of(const float4* x, int plane, bool& zero)
{
    const int c = plane % C_DIM;
    const int t = (plane / C_DIM) % N_FRAME;
    const float4* s = x + (size_t)plane * HW4;
    zero = false;
    if (c < FOLD) {
        if (t < N_FRAME - 1) s += (size_t)C_DIM * HW4;     // read t+1
        else zero = true;
    } else if (c < 2 * FOLD) {
        if (t > 0) s -= (size_t)C_DIM * HW4;               // read t-1
        else zero = true;
    }
    return s;
}

__global__ __launch_bounds__(256, 6) void tsm_shift_kernel(
    const float4* __restrict__ x, float4* __restrict__ out)
{
    const int p0 = blockIdx.x * 2;
    const int p1 = p0 + 1;
    const int tid = threadIdx.x;
    const bool tail = (tid < HW4 - 3 * 256);               // tid < 16

    bool z0, z1;
    const float4* s0 = src_of(x, p0, z0);
    const float4* s1 = src_of(x, p1, z1);
    float4* d0 = out + (size_t)p0 * HW4;
    float4* d1 = out + (size_t)p1 * HW4;

    const float4 zv = make_float4(0.f, 0.f, 0.f, 0.f);
    float4 v0 = zv, v1 = zv, v2 = zv, v3 = zv;
    float4 u0 = zv, u1 = zv, u2 = zv, u3 = zv;

    // Front-batch all loads (up to 8 independent LDG.128.CS per thread).
    if (!z0) {
        v0 = __ldcs(s0 + tid);
        v1 = __ldcs(s0 + tid + 256);
        v2 = __ldcs(s0 + tid + 512);
        if (tail) v3 = __ldcs(s0 + tid + 768);
    }
    if (!z1) {
        u0 = __ldcs(s1 + tid);
        u1 = __ldcs(s1 + tid + 256);
        u2 = __ldcs(s1 + tid + 512);
        if (tail) u3 = __ldcs(s1 + tid + 768);
    }

    // Then all stores.
    __stcs(d0 + tid,       v0);
    __stcs(d0 + tid + 256, v1);
    __stcs(d0 + tid + 512, v2);
    if (tail) __stcs(d0 + tid + 768, v3);
    __stcs(d1 + tid,       u0);
    __stcs(d1 + tid + 256, u1);
    __stcs(d1 + tid + 512, u2);
    if (tail) __stcs(d1 + tid + 768, u3);
}

extern "C" void kernel_launch(void* const* d_in, const int* in_sizes, int n_in,
                              void* d_out, int out_size)
{
    const float4* x = (const float4*)d_in[0];
    float4* out = (float4*)d_out;
    tsm_shift_kernel<<<N_PLANES / 2, 256>>>(x, out);   // 6144 CTAs, 2 planes each
}